// round 2
// baseline (speedup 1.0000x reference)
#include <cuda_runtime.h>
#include <cuda_bf16.h>
#include <math.h>

#define N_NODES 50000
#define N_EDGES 800000
#define N_GRAPHS 512
#define IN_DIM 126
#define DIMH 128
#define LIN1_DIM 64
#define BN_EPS 1e-5f

// ---------------- device scratch (no allocations allowed) ----------------
__device__ float g_feat[N_NODES * DIMH];   // current layer features (padded)
__device__ float g_a[N_NODES * DIMH];      // x + agg
__device__ float g_h[N_NODES * DIMH];      // after first MLP linear
__device__ int   g_cnt[N_NODES];
__device__ int   g_off[N_NODES + 1];
__device__ int   g_cur[N_NODES];
__device__ int   g_srcs[N_EDGES];
__device__ float g_pool[N_GRAPHS * DIMH];

// ---------------- small utility kernels ----------------
__global__ void zero_int_kernel(int* p, int n) {
    int i = blockIdx.x * blockDim.x + threadIdx.x;
    if (i < n) p[i] = 0;
}
__global__ void zero_float_kernel(float* p, int n) {
    int i = blockIdx.x * blockDim.x + threadIdx.x;
    if (i < n) p[i] = 0.0f;
}

__global__ void count_kernel(const int* __restrict__ dst) {
    int i = blockIdx.x * blockDim.x + threadIdx.x;
    if (i < N_EDGES) atomicAdd(&g_cnt[dst[i]], 1);
}

// single-block exclusive scan over g_cnt -> g_off (n = N_NODES)
__global__ void scan_kernel(int n) {
    __shared__ int warp_sums[32];
    __shared__ int s_carry;
    int tid = threadIdx.x;
    int lane = tid & 31, wid = tid >> 5;
    const int NW = 32;  // 1024 threads
    if (tid == 0) s_carry = 0;
    __syncthreads();
    for (int base = 0; base < n; base += blockDim.x) {
        int i = base + tid;
        int v = (i < n) ? g_cnt[i] : 0;
        int x = v;
        #pragma unroll
        for (int o = 1; o < 32; o <<= 1) {
            int t = __shfl_up_sync(0xFFFFFFFFu, x, o);
            if (lane >= o) x += t;
        }
        if (lane == 31) warp_sums[wid] = x;
        __syncthreads();
        if (wid == 0) {
            int s = (lane < NW) ? warp_sums[lane] : 0;
            #pragma unroll
            for (int o = 1; o < 32; o <<= 1) {
                int t = __shfl_up_sync(0xFFFFFFFFu, s, o);
                if (lane >= o) s += t;
            }
            warp_sums[lane] = s;
        }
        __syncthreads();
        int excl = s_carry + x - v + (wid > 0 ? warp_sums[wid - 1] : 0);
        if (i < n) g_off[i] = excl;
        __syncthreads();
        if (tid == 0) s_carry += warp_sums[NW - 1];
        __syncthreads();
    }
    if (threadIdx.x == 0) g_off[n] = s_carry;
}

__global__ void copy_cursor_kernel() {
    int i = blockIdx.x * blockDim.x + threadIdx.x;
    if (i < N_NODES) g_cur[i] = g_off[i];
}

__global__ void scatter_kernel(const int* __restrict__ src, const int* __restrict__ dst) {
    int i = blockIdx.x * blockDim.x + threadIdx.x;
    if (i < N_EDGES) {
        int p = atomicAdd(&g_cur[dst[i]], 1);
        g_srcs[p] = src[i];
    }
}

__global__ void pad_x_kernel(const float* __restrict__ x) {
    int i = blockIdx.x * blockDim.x + threadIdx.x;
    if (i < N_NODES * DIMH) {
        int n = i >> 7, d = i & 127;
        g_feat[i] = (d < IN_DIM) ? x[n * IN_DIM + d] : 0.0f;
    }
}

// ---------------- aggregation: out[node] = F[node] + sum_{src->node} F[src]
__global__ void agg_kernel(const float* __restrict__ F, float* __restrict__ out) {
    int node = blockIdx.x;
    int d = threadIdx.x;  // 128 threads
    int s = g_off[node], e = g_off[node + 1];
    float acc = F[node * DIMH + d];
    __shared__ int sn[128];
    for (int base = s; base < e; base += 128) {
        int cnt = min(128, e - base);
        if (d < cnt) sn[d] = g_srcs[base + d];
        __syncthreads();
        float a0 = 0.f, a1 = 0.f, a2 = 0.f, a3 = 0.f;
        int i = 0;
        for (; i + 4 <= cnt; i += 4) {
            a0 += F[sn[i + 0] * DIMH + d];
            a1 += F[sn[i + 1] * DIMH + d];
            a2 += F[sn[i + 2] * DIMH + d];
            a3 += F[sn[i + 3] * DIMH + d];
        }
        for (; i < cnt; i++) a0 += F[sn[i] * DIMH + d];
        acc += (a0 + a1) + (a2 + a3);
        __syncthreads();
    }
    out[node * DIMH + d] = acc;
}

// ---------------- fused GEMM: C = epilogue(A[M,128] @ W[Kw,128] + bias)
// mode 0: bias -> BN(eval) -> ReLU ; mode 1: bias -> ReLU
__global__ __launch_bounds__(256) void gemm_kernel(
    const float* __restrict__ A, const float* __restrict__ W,
    const float* __restrict__ bias,
    const float* __restrict__ gamma, const float* __restrict__ beta,
    const float* __restrict__ mean, const float* __restrict__ var,
    float* __restrict__ C, int M, int Kw, int mode)
{
    __shared__ float As[128][36];
    __shared__ float Bs[32][132];

    int tid = threadIdx.x;          // 256
    int tx = tid & 15;              // col group
    int ty = tid >> 4;              // row group
    int row0 = blockIdx.x * 128;

    float acc[8][8];
    #pragma unroll
    for (int i = 0; i < 8; i++)
        #pragma unroll
        for (int j = 0; j < 8; j++) acc[i][j] = 0.0f;

    for (int k0 = 0; k0 < 128; k0 += 32) {
        #pragma unroll
        for (int l = 0; l < 4; l++) {
            int idx = tid + l * 256;
            int r = idx >> 3, c4 = (idx & 7) * 4;
            int gr = row0 + r;
            float4 v = make_float4(0.f, 0.f, 0.f, 0.f);
            if (gr < M) v = *(const float4*)&A[gr * DIMH + k0 + c4];
            *(float4*)&As[r][c4] = v;
        }
        #pragma unroll
        for (int l = 0; l < 4; l++) {
            int idx = tid + l * 256;
            int r = idx >> 5, c4 = (idx & 31) * 4;
            int gk = k0 + r;
            float4 v = make_float4(0.f, 0.f, 0.f, 0.f);
            if (gk < Kw) v = *(const float4*)&W[gk * DIMH + c4];
            *(float4*)&Bs[r][c4] = v;
        }
        __syncthreads();

        #pragma unroll
        for (int kk = 0; kk < 32; kk++) {
            float a[8], b[8];
            #pragma unroll
            for (int i = 0; i < 8; i++) a[i] = As[ty * 8 + i][kk];
            float4 b0 = *(float4*)&Bs[kk][tx * 8];
            float4 b1 = *(float4*)&Bs[kk][tx * 8 + 4];
            b[0] = b0.x; b[1] = b0.y; b[2] = b0.z; b[3] = b0.w;
            b[4] = b1.x; b[5] = b1.y; b[6] = b1.z; b[7] = b1.w;
            #pragma unroll
            for (int i = 0; i < 8; i++)
                #pragma unroll
                for (int j = 0; j < 8; j++)
                    acc[i][j] = fmaf(a[i], b[j], acc[i][j]);
        }
        __syncthreads();
    }

    float sc[8], sh[8];
    #pragma unroll
    for (int j = 0; j < 8; j++) {
        int c = tx * 8 + j;
        float b = bias[c];
        if (mode == 0) {
            float s = gamma[c] * rsqrtf(var[c] + BN_EPS);
            sc[j] = s;
            sh[j] = beta[c] - mean[c] * s + b * s;
        } else {
            sc[j] = 1.0f;
            sh[j] = b;
        }
    }
    #pragma unroll
    for (int i = 0; i < 8; i++) {
        int row = row0 + ty * 8 + i;
        if (row >= M) continue;
        float out[8];
        #pragma unroll
        for (int j = 0; j < 8; j++)
            out[j] = fmaxf(acc[i][j] * sc[j] + sh[j], 0.0f);
        *(float4*)&C[row * DIMH + tx * 8]     = make_float4(out[0], out[1], out[2], out[3]);
        *(float4*)&C[row * DIMH + tx * 8 + 4] = make_float4(out[4], out[5], out[6], out[7]);
    }
}

// ---------------- pooling: pool[batch[n]] += h[n]
__global__ void pool_kernel(const int* __restrict__ batch, const float* __restrict__ h,
                            float* __restrict__ pool) {
    int i = blockIdx.x * blockDim.x + threadIdx.x;
    if (i < N_NODES * DIMH) {
        int n = i >> 7, d = i & 127;
        atomicAdd(&pool[batch[n] * DIMH + d], h[i]);
    }
}

// ---------------- head: relu(pool @ l1_w + l1_b) @ l2_w + l2_b -> sigmoid
__global__ void head_kernel(const float* __restrict__ pool,
                            const float* __restrict__ l1w, const float* __restrict__ l1b,
                            const float* __restrict__ l2w, const float* __restrict__ l2b,
                            float* __restrict__ out) {
    __shared__ float hg[DIMH];
    __shared__ float o1[LIN1_DIM];
    int g = blockIdx.x;
    int t = threadIdx.x;  // 128
    hg[t] = pool[g * DIMH + t];
    __syncthreads();
    if (t < LIN1_DIM) {
        float s = l1b[t];
        #pragma unroll 8
        for (int k = 0; k < DIMH; k++) s += hg[k] * l1w[k * LIN1_DIM + t];
        o1[t] = fmaxf(s, 0.0f);
    }
    __syncthreads();
    if (t == 0) {
        float s = l2b[0];
        #pragma unroll 8
        for (int j = 0; j < LIN1_DIM; j++) s += o1[j] * l2w[j];
        out[g] = 1.0f / (1.0f + expf(-s));
    }
}

// ---------------- launch ----------------
extern "C" void kernel_launch(void* const* d_in, const int* in_sizes, int n_in,
                              void* d_out, int out_size) {
    const float* x          = (const float*)d_in[0];
    const int*   edge_index = (const int*)d_in[1];
    const int*   batch      = (const int*)d_in[2];
    const float* w[3][7];
    const float* b2[3];
    for (int l = 0; l < 3; l++) {
        int base = 3 + l * 8;
        w[l][0] = (const float*)d_in[base + 0];  // w1
        w[l][1] = (const float*)d_in[base + 1];  // b1
        w[l][2] = (const float*)d_in[base + 2];  // gamma
        w[l][3] = (const float*)d_in[base + 3];  // beta
        w[l][4] = (const float*)d_in[base + 4];  // mean
        w[l][5] = (const float*)d_in[base + 5];  // var
        w[l][6] = (const float*)d_in[base + 6];  // w2
        b2[l]   = (const float*)d_in[base + 7];  // b2
    }
    const float* l1w = (const float*)d_in[27];
    const float* l1b = (const float*)d_in[28];
    const float* l2w = (const float*)d_in[29];
    const float* l2b = (const float*)d_in[30];
    float* out = (float*)d_out;

    const int* e_src = edge_index;            // row 0
    const int* e_dst = edge_index + N_EDGES;  // row 1

    // Resolve ALL device-symbol addresses via host API (capture-safe, once).
    // NOTE: passing __device__ symbols directly as kernel args from host code
    // yields the host shadow address (silently wrong on ATS systems) — must
    // use cudaGetSymbolAddress.
    static float* p_feat = nullptr;
    static float* p_a    = nullptr;
    static float* p_h    = nullptr;
    static int*   p_cnt  = nullptr;
    static float* p_pool = nullptr;
    if (!p_feat) {
        cudaGetSymbolAddress((void**)&p_feat, g_feat);
        cudaGetSymbolAddress((void**)&p_a,    g_a);
        cudaGetSymbolAddress((void**)&p_h,    g_h);
        cudaGetSymbolAddress((void**)&p_cnt,  g_cnt);
        cudaGetSymbolAddress((void**)&p_pool, g_pool);
    }

    // ---- CSR build ----
    zero_int_kernel<<<(N_NODES + 255) / 256, 256>>>(p_cnt, N_NODES);
    count_kernel<<<(N_EDGES + 255) / 256, 256>>>(e_dst);
    scan_kernel<<<1, 1024>>>(N_NODES);
    copy_cursor_kernel<<<(N_NODES + 255) / 256, 256>>>();
    scatter_kernel<<<(N_EDGES + 255) / 256, 256>>>(e_src, e_dst);

    // ---- pad x to 128 ----
    pad_x_kernel<<<(N_NODES * DIMH + 255) / 256, 256>>>(x);

    const int GEMM_GRID = (N_NODES + 127) / 128;

    // ---- 3 GIN layers ----
    for (int l = 0; l < 3; l++) {
        int Kw = (l == 0) ? IN_DIM : DIMH;
        agg_kernel<<<N_NODES, 128>>>(p_feat, p_a);
        gemm_kernel<<<GEMM_GRID, 256>>>(p_a, w[l][0], w[l][1],
                                        w[l][2], w[l][3], w[l][4], w[l][5],
                                        p_h, N_NODES, Kw, /*mode=*/0);
        gemm_kernel<<<GEMM_GRID, 256>>>(p_h, w[l][6], b2[l],
                                        nullptr, nullptr, nullptr, nullptr,
                                        p_feat, N_NODES, DIMH, /*mode=*/1);
    }

    // ---- global add pool + head ----
    zero_float_kernel<<<(N_GRAPHS * DIMH + 255) / 256, 256>>>(p_pool, N_GRAPHS * DIMH);
    pool_kernel<<<(N_NODES * DIMH + 255) / 256, 256>>>(batch, p_feat, p_pool);
    head_kernel<<<N_GRAPHS, 128>>>(p_pool, l1w, l1b, l2w, l2b, out);
}

// round 3
// speedup vs baseline: 1.2584x; 1.2584x over previous
#include <cuda_runtime.h>
#include <cuda_bf16.h>
#include <math.h>
#include <stdint.h>

#define N_NODES 50000
#define N_EDGES 800000
#define N_GRAPHS 512
#define IN_DIM 126
#define DIMH 128
#define LIN1_DIM 64
#define BN_EPS 1e-5f

// ---------------- device scratch (no allocations allowed) ----------------
__device__ float g_feat[N_NODES * DIMH];
__device__ float g_a[N_NODES * DIMH];
__device__ float g_h[N_NODES * DIMH];
__device__ int   g_cnt[N_NODES];
__device__ int   g_off[N_NODES + 1];
__device__ int   g_cur[N_NODES];
__device__ int   g_srcs[N_EDGES];
__device__ float g_pool[N_GRAPHS * DIMH];

// ---------------- small utility kernels ----------------
__global__ void zero_int_kernel(int* p, int n) {
    int i = blockIdx.x * blockDim.x + threadIdx.x;
    if (i < n) p[i] = 0;
}
__global__ void zero_float_kernel(float* p, int n) {
    int i = blockIdx.x * blockDim.x + threadIdx.x;
    if (i < n) p[i] = 0.0f;
}

__global__ void count_kernel(const int* __restrict__ dst) {
    int i = blockIdx.x * blockDim.x + threadIdx.x;
    if (i < N_EDGES) atomicAdd(&g_cnt[dst[i]], 1);
}

__global__ void scan_kernel(int n) {
    __shared__ int warp_sums[32];
    __shared__ int s_carry;
    int tid = threadIdx.x;
    int lane = tid & 31, wid = tid >> 5;
    const int NW = 32;
    if (tid == 0) s_carry = 0;
    __syncthreads();
    for (int base = 0; base < n; base += blockDim.x) {
        int i = base + tid;
        int v = (i < n) ? g_cnt[i] : 0;
        int x = v;
        #pragma unroll
        for (int o = 1; o < 32; o <<= 1) {
            int t = __shfl_up_sync(0xFFFFFFFFu, x, o);
            if (lane >= o) x += t;
        }
        if (lane == 31) warp_sums[wid] = x;
        __syncthreads();
        if (wid == 0) {
            int s = (lane < NW) ? warp_sums[lane] : 0;
            #pragma unroll
            for (int o = 1; o < 32; o <<= 1) {
                int t = __shfl_up_sync(0xFFFFFFFFu, s, o);
                if (lane >= o) s += t;
            }
            warp_sums[lane] = s;
        }
        __syncthreads();
        int excl = s_carry + x - v + (wid > 0 ? warp_sums[wid - 1] : 0);
        if (i < n) g_off[i] = excl;
        __syncthreads();
        if (tid == 0) s_carry += warp_sums[NW - 1];
        __syncthreads();
    }
    if (threadIdx.x == 0) g_off[n] = s_carry;
}

__global__ void copy_cursor_kernel() {
    int i = blockIdx.x * blockDim.x + threadIdx.x;
    if (i < N_NODES) g_cur[i] = g_off[i];
}

__global__ void scatter_kernel(const int* __restrict__ src, const int* __restrict__ dst) {
    int i = blockIdx.x * blockDim.x + threadIdx.x;
    if (i < N_EDGES) {
        int p = atomicAdd(&g_cur[dst[i]], 1);
        g_srcs[p] = src[i];
    }
}

__global__ void pad_x_kernel(const float* __restrict__ x) {
    int i = blockIdx.x * blockDim.x + threadIdx.x;
    if (i < N_NODES * DIMH) {
        int n = i >> 7, d = i & 127;
        g_feat[i] = (d < IN_DIM) ? x[n * IN_DIM + d] : 0.0f;
    }
}

// ---------------- aggregation: out[node] = F[node] + sum_{src->node} F[src]
__global__ void agg_kernel(const float* __restrict__ F, float* __restrict__ out) {
    int node = blockIdx.x;
    int d = threadIdx.x;  // 128
    int s = g_off[node], e = g_off[node + 1];
    float acc = F[node * DIMH + d];
    __shared__ int sn[128];
    for (int base = s; base < e; base += 128) {
        int cnt = min(128, e - base);
        if (d < cnt) sn[d] = g_srcs[base + d];
        __syncthreads();
        float a0 = 0.f, a1 = 0.f, a2 = 0.f, a3 = 0.f;
        int i = 0;
        for (; i + 4 <= cnt; i += 4) {
            a0 += F[sn[i + 0] * DIMH + d];
            a1 += F[sn[i + 1] * DIMH + d];
            a2 += F[sn[i + 2] * DIMH + d];
            a3 += F[sn[i + 3] * DIMH + d];
        }
        for (; i < cnt; i++) a0 += F[sn[i] * DIMH + d];
        acc += (a0 + a1) + (a2 + a3);
        __syncthreads();
    }
    out[node * DIMH + d] = acc;
}

// ---------------- tensor-core GEMM (3xTF32, fp32-grade accuracy) ----------
__device__ __forceinline__ uint32_t f2tf32(float x) {
    uint32_t r;
    asm("cvt.rna.tf32.f32 %0, %1;" : "=r"(r) : "f"(x));
    return r;
}
__device__ __forceinline__ void mma_tf32(float* c, const uint32_t* a, const uint32_t* b) {
    asm volatile(
        "mma.sync.aligned.m16n8k8.row.col.f32.tf32.tf32.f32 "
        "{%0,%1,%2,%3}, {%4,%5,%6,%7}, {%8,%9}, {%0,%1,%2,%3};\n"
        : "+f"(c[0]), "+f"(c[1]), "+f"(c[2]), "+f"(c[3])
        : "r"(a[0]), "r"(a[1]), "r"(a[2]), "r"(a[3]), "r"(b[0]), "r"(b[1]));
}

// C = epilogue(A[M,128] @ W[Kw<=128,128] + bias); mode 0: +BN+ReLU, mode 1: +ReLU
// Block tile 128x128, 8 warps (2x4), warp tile 64x32, K-chunk 32.
#define AST 36    // A smem stride (floats): bank = 4*row+col bijective on 8x4 frag
#define BST 136   // B smem stride (floats): bank = 8*k+n   bijective on 4x8 frag
__global__ __launch_bounds__(256, 2) void gemm_tc_kernel(
    const float* __restrict__ A, const float* __restrict__ W,
    const float* __restrict__ bias,
    const float* __restrict__ gamma, const float* __restrict__ beta,
    const float* __restrict__ mean, const float* __restrict__ var,
    float* __restrict__ C, int M, int Kw, int mode)
{
    __shared__ float Ah[128][AST];
    __shared__ float Al[128][AST];
    __shared__ float Bh[32][BST];
    __shared__ float Bl[32][BST];

    const int tid  = threadIdx.x;
    const int wid  = tid >> 5;
    const int lane = tid & 31;
    const int g    = lane >> 2;   // groupID
    const int tig  = lane & 3;    // thread-in-group
    const int wm   = wid & 1;     // warp row (2 x 64)
    const int wn   = wid >> 1;    // warp col (4 x 32)
    const int row0 = blockIdx.x * 128;

    float acc[4][4][4];
    #pragma unroll
    for (int mi = 0; mi < 4; mi++)
        #pragma unroll
        for (int ni = 0; ni < 4; ni++)
            #pragma unroll
            for (int r = 0; r < 4; r++) acc[mi][ni][r] = 0.0f;

    for (int k0 = 0; k0 < 128; k0 += 32) {
        // ---- load A chunk 128x32 (4 float4/thread), split hi/lo ----
        #pragma unroll
        for (int l = 0; l < 4; l++) {
            int idx = tid + l * 256;
            int r = idx >> 3, c4 = (idx & 7) * 4;
            int gr = row0 + r;
            float4 v = make_float4(0.f, 0.f, 0.f, 0.f);
            if (gr < M) v = *(const float4*)&A[gr * DIMH + k0 + c4];
            float hx = __uint_as_float(f2tf32(v.x));
            float hy = __uint_as_float(f2tf32(v.y));
            float hz = __uint_as_float(f2tf32(v.z));
            float hw = __uint_as_float(f2tf32(v.w));
            *(float4*)&Ah[r][c4] = make_float4(hx, hy, hz, hw);
            *(float4*)&Al[r][c4] = make_float4(
                __uint_as_float(f2tf32(v.x - hx)), __uint_as_float(f2tf32(v.y - hy)),
                __uint_as_float(f2tf32(v.z - hz)), __uint_as_float(f2tf32(v.w - hw)));
        }
        // ---- load W chunk 32x128 (4 float4/thread), split hi/lo ----
        #pragma unroll
        for (int l = 0; l < 4; l++) {
            int idx = tid + l * 256;
            int r = idx >> 5, c4 = (idx & 31) * 4;
            int gk = k0 + r;
            float4 v = make_float4(0.f, 0.f, 0.f, 0.f);
            if (gk < Kw) v = *(const float4*)&W[gk * DIMH + c4];
            float hx = __uint_as_float(f2tf32(v.x));
            float hy = __uint_as_float(f2tf32(v.y));
            float hz = __uint_as_float(f2tf32(v.z));
            float hw = __uint_as_float(f2tf32(v.w));
            *(float4*)&Bh[r][c4] = make_float4(hx, hy, hz, hw);
            *(float4*)&Bl[r][c4] = make_float4(
                __uint_as_float(f2tf32(v.x - hx)), __uint_as_float(f2tf32(v.y - hy)),
                __uint_as_float(f2tf32(v.z - hz)), __uint_as_float(f2tf32(v.w - hw)));
        }
        __syncthreads();

        #pragma unroll
        for (int ks = 0; ks < 4; ks++) {
            const int kk = ks * 8;
            uint32_t a_hi[4][4], a_lo[4][4];
            #pragma unroll
            for (int mi = 0; mi < 4; mi++) {
                int rm = wm * 64 + mi * 16;
                a_hi[mi][0] = __float_as_uint(Ah[rm + g    ][kk + tig    ]);
                a_hi[mi][1] = __float_as_uint(Ah[rm + g + 8][kk + tig    ]);
                a_hi[mi][2] = __float_as_uint(Ah[rm + g    ][kk + tig + 4]);
                a_hi[mi][3] = __float_as_uint(Ah[rm + g + 8][kk + tig + 4]);
                a_lo[mi][0] = __float_as_uint(Al[rm + g    ][kk + tig    ]);
                a_lo[mi][1] = __float_as_uint(Al[rm + g + 8][kk + tig    ]);
                a_lo[mi][2] = __float_as_uint(Al[rm + g    ][kk + tig + 4]);
                a_lo[mi][3] = __float_as_uint(Al[rm + g + 8][kk + tig + 4]);
            }
            #pragma unroll
            for (int ni = 0; ni < 4; ni++) {
                int cn = wn * 32 + ni * 8;
                uint32_t bh[2], bl[2];
                bh[0] = __float_as_uint(Bh[kk + tig    ][cn + g]);
                bh[1] = __float_as_uint(Bh[kk + tig + 4][cn + g]);
                bl[0] = __float_as_uint(Bl[kk + tig    ][cn + g]);
                bl[1] = __float_as_uint(Bl[kk + tig + 4][cn + g]);
                #pragma unroll
                for (int mi = 0; mi < 4; mi++) {
                    mma_tf32(acc[mi][ni], a_hi[mi], bh);
                    mma_tf32(acc[mi][ni], a_hi[mi], bl);
                    mma_tf32(acc[mi][ni], a_lo[mi], bh);
                }
            }
        }
        __syncthreads();
    }

    // ---- epilogue: per-column scale/shift then ReLU ----
    float sc[4][2], sh[4][2];
    #pragma unroll
    for (int ni = 0; ni < 4; ni++) {
        #pragma unroll
        for (int j = 0; j < 2; j++) {
            int c = wn * 32 + ni * 8 + 2 * tig + j;
            float b = bias[c];
            if (mode == 0) {
                float s = gamma[c] * rsqrtf(var[c] + BN_EPS);
                sc[ni][j] = s;
                sh[ni][j] = beta[c] - mean[c] * s + b * s;
            } else {
                sc[ni][j] = 1.0f;
                sh[ni][j] = b;
            }
        }
    }
    #pragma unroll
    for (int mi = 0; mi < 4; mi++) {
        int r0 = row0 + wm * 64 + mi * 16 + g;
        int r1 = r0 + 8;
        #pragma unroll
        for (int ni = 0; ni < 4; ni++) {
            int c0 = wn * 32 + ni * 8 + 2 * tig;
            if (r0 < M) {
                float2 o;
                o.x = fmaxf(acc[mi][ni][0] * sc[ni][0] + sh[ni][0], 0.0f);
                o.y = fmaxf(acc[mi][ni][1] * sc[ni][1] + sh[ni][1], 0.0f);
                *(float2*)&C[r0 * DIMH + c0] = o;
            }
            if (r1 < M) {
                float2 o;
                o.x = fmaxf(acc[mi][ni][2] * sc[ni][0] + sh[ni][0], 0.0f);
                o.y = fmaxf(acc[mi][ni][3] * sc[ni][1] + sh[ni][1], 0.0f);
                *(float2*)&C[r1 * DIMH + c0] = o;
            }
        }
    }
}

// ---------------- pooling: pool[batch[n]] += h[n]
__global__ void pool_kernel(const int* __restrict__ batch, const float* __restrict__ h,
                            float* __restrict__ pool) {
    int i = blockIdx.x * blockDim.x + threadIdx.x;
    if (i < N_NODES * DIMH) {
        int n = i >> 7, d = i & 127;
        atomicAdd(&pool[batch[n] * DIMH + d], h[i]);
    }
}

// ---------------- head
__global__ void head_kernel(const float* __restrict__ pool,
                            const float* __restrict__ l1w, const float* __restrict__ l1b,
                            const float* __restrict__ l2w, const float* __restrict__ l2b,
                            float* __restrict__ out) {
    __shared__ float hg[DIMH];
    __shared__ float o1[LIN1_DIM];
    int gph = blockIdx.x;
    int t = threadIdx.x;  // 128
    hg[t] = pool[gph * DIMH + t];
    __syncthreads();
    if (t < LIN1_DIM) {
        float s = l1b[t];
        #pragma unroll 8
        for (int k = 0; k < DIMH; k++) s += hg[k] * l1w[k * LIN1_DIM + t];
        o1[t] = fmaxf(s, 0.0f);
    }
    __syncthreads();
    if (t == 0) {
        float s = l2b[0];
        #pragma unroll 8
        for (int j = 0; j < LIN1_DIM; j++) s += o1[j] * l2w[j];
        out[gph] = 1.0f / (1.0f + expf(-s));
    }
}

// ---------------- launch ----------------
extern "C" void kernel_launch(void* const* d_in, const int* in_sizes, int n_in,
                              void* d_out, int out_size) {
    const float* x          = (const float*)d_in[0];
    const int*   edge_index = (const int*)d_in[1];
    const int*   batch      = (const int*)d_in[2];
    const float* w[3][7];
    const float* b2[3];
    for (int l = 0; l < 3; l++) {
        int base = 3 + l * 8;
        w[l][0] = (const float*)d_in[base + 0];
        w[l][1] = (const float*)d_in[base + 1];
        w[l][2] = (const float*)d_in[base + 2];
        w[l][3] = (const float*)d_in[base + 3];
        w[l][4] = (const float*)d_in[base + 4];
        w[l][5] = (const float*)d_in[base + 5];
        w[l][6] = (const float*)d_in[base + 6];
        b2[l]   = (const float*)d_in[base + 7];
    }
    const float* l1w = (const float*)d_in[27];
    const float* l1b = (const float*)d_in[28];
    const float* l2w = (const float*)d_in[29];
    const float* l2b = (const float*)d_in[30];
    float* out = (float*)d_out;

    const int* e_src = edge_index;
    const int* e_dst = edge_index + N_EDGES;

    static float* p_feat = nullptr;
    static float* p_a    = nullptr;
    static float* p_h    = nullptr;
    static int*   p_cnt  = nullptr;
    static float* p_pool = nullptr;
    if (!p_feat) {
        cudaGetSymbolAddress((void**)&p_feat, g_feat);
        cudaGetSymbolAddress((void**)&p_a,    g_a);
        cudaGetSymbolAddress((void**)&p_h,    g_h);
        cudaGetSymbolAddress((void**)&p_cnt,  g_cnt);
        cudaGetSymbolAddress((void**)&p_pool, g_pool);
    }

    // ---- CSR build ----
    zero_int_kernel<<<(N_NODES + 255) / 256, 256>>>(p_cnt, N_NODES);
    count_kernel<<<(N_EDGES + 255) / 256, 256>>>(e_dst);
    scan_kernel<<<1, 1024>>>(N_NODES);
    copy_cursor_kernel<<<(N_NODES + 255) / 256, 256>>>();
    scatter_kernel<<<(N_EDGES + 255) / 256, 256>>>(e_src, e_dst);

    // ---- pad x to 128 ----
    pad_x_kernel<<<(N_NODES * DIMH + 255) / 256, 256>>>(x);

    const int GEMM_GRID = (N_NODES + 127) / 128;

    // ---- 3 GIN layers ----
    for (int l = 0; l < 3; l++) {
        int Kw = (l == 0) ? IN_DIM : DIMH;
        agg_kernel<<<N_NODES, 128>>>(p_feat, p_a);
        gemm_tc_kernel<<<GEMM_GRID, 256>>>(p_a, w[l][0], w[l][1],
                                           w[l][2], w[l][3], w[l][4], w[l][5],
                                           p_h, N_NODES, Kw, /*mode=*/0);
        gemm_tc_kernel<<<GEMM_GRID, 256>>>(p_h, w[l][6], b2[l],
                                           nullptr, nullptr, nullptr, nullptr,
                                           p_feat, N_NODES, DIMH, /*mode=*/1);
    }

    // ---- global add pool + head ----
    zero_float_kernel<<<(N_GRAPHS * DIMH + 255) / 256, 256>>>(p_pool, N_GRAPHS * DIMH);
    pool_kernel<<<(N_NODES * DIMH + 255) / 256, 256>>>(batch, p_feat, p_pool);
    head_kernel<<<N_GRAPHS, 128>>>(p_pool, l1w, l1b, l2w, l2b, out);
}

// round 4
// speedup vs baseline: 1.6784x; 1.3337x over previous
#include <cuda_runtime.h>
#include <cuda_bf16.h>
#include <math.h>
#include <stdint.h>

#define N_NODES 50000
#define N_EDGES 800000
#define N_GRAPHS 512
#define IN_DIM 126
#define DIMH 128
#define LIN1_DIM 64
#define BN_EPS 1e-5f

// ---------------- device scratch ----------------
__device__ float g_feat[N_NODES * DIMH];
__device__ float g_a[N_NODES * DIMH];
__device__ float g_h[N_NODES * DIMH];
__device__ int   g_cnt[N_NODES];
__device__ int   g_off[N_NODES + 1];
__device__ int   g_cur[N_NODES];
__device__ int   g_srcs[N_EDGES];
__device__ float g_pool[N_GRAPHS * DIMH];

// ---------------- utility kernels ----------------
__global__ void zero_int_kernel(int* p, int n) {
    int i = blockIdx.x * blockDim.x + threadIdx.x;
    if (i < n) p[i] = 0;
}
__global__ void zero_float_kernel(float* p, int n) {
    int i = blockIdx.x * blockDim.x + threadIdx.x;
    if (i < n) p[i] = 0.0f;
}
__global__ void count_kernel(const int* __restrict__ dst) {
    int i = blockIdx.x * blockDim.x + threadIdx.x;
    if (i < N_EDGES) atomicAdd(&g_cnt[dst[i]], 1);
}

// exclusive scan over g_cnt -> g_off AND g_cur (single block)
__global__ void scan_kernel(int n) {
    __shared__ int warp_sums[32];
    __shared__ int s_carry;
    int tid = threadIdx.x;
    int lane = tid & 31, wid = tid >> 5;
    const int NW = 32;
    if (tid == 0) s_carry = 0;
    __syncthreads();
    for (int base = 0; base < n; base += blockDim.x) {
        int i = base + tid;
        int v = (i < n) ? g_cnt[i] : 0;
        int x = v;
        #pragma unroll
        for (int o = 1; o < 32; o <<= 1) {
            int t = __shfl_up_sync(0xFFFFFFFFu, x, o);
            if (lane >= o) x += t;
        }
        if (lane == 31) warp_sums[wid] = x;
        __syncthreads();
        if (wid == 0) {
            int s = (lane < NW) ? warp_sums[lane] : 0;
            #pragma unroll
            for (int o = 1; o < 32; o <<= 1) {
                int t = __shfl_up_sync(0xFFFFFFFFu, s, o);
                if (lane >= o) s += t;
            }
            warp_sums[lane] = s;
        }
        __syncthreads();
        int excl = s_carry + x - v + (wid > 0 ? warp_sums[wid - 1] : 0);
        if (i < n) { g_off[i] = excl; g_cur[i] = excl; }
        __syncthreads();
        if (tid == 0) s_carry += warp_sums[NW - 1];
        __syncthreads();
    }
    if (threadIdx.x == 0) g_off[n] = s_carry;
}

__global__ void scatter_kernel(const int* __restrict__ src, const int* __restrict__ dst) {
    int i = blockIdx.x * blockDim.x + threadIdx.x;
    if (i < N_EDGES) {
        int p = atomicAdd(&g_cur[dst[i]], 1);
        g_srcs[p] = src[i];
    }
}

__global__ void pad_x_kernel(const float* __restrict__ x) {
    int i = blockIdx.x * blockDim.x + threadIdx.x;
    if (i < N_NODES * DIMH) {
        int n = i >> 7, d = i & 127;
        g_feat[i] = (d < IN_DIM) ? x[n * IN_DIM + d] : 0.0f;
    }
}

// ---------------- aggregation: warp per node, float4 lanes ----------------
__global__ __launch_bounds__(256) void agg_kernel(const float* __restrict__ F,
                                                  float* __restrict__ out) {
    int warp = (blockIdx.x * blockDim.x + threadIdx.x) >> 5;
    int lane = threadIdx.x & 31;
    if (warp >= N_NODES) return;
    int s = g_off[warp], e = g_off[warp + 1];
    float4 acc = *(const float4*)&F[warp * DIMH + lane * 4];
    for (int base = s; base < e; base += 32) {
        int cnt = min(32, e - base);
        int idx = (base + lane < e) ? g_srcs[base + lane] : 0;
        int j = 0;
        for (; j + 4 <= cnt; j += 4) {
            int s0 = __shfl_sync(0xFFFFFFFFu, idx, j);
            int s1 = __shfl_sync(0xFFFFFFFFu, idx, j + 1);
            int s2 = __shfl_sync(0xFFFFFFFFu, idx, j + 2);
            int s3 = __shfl_sync(0xFFFFFFFFu, idx, j + 3);
            float4 v0 = *(const float4*)&F[s0 * DIMH + lane * 4];
            float4 v1 = *(const float4*)&F[s1 * DIMH + lane * 4];
            float4 v2 = *(const float4*)&F[s2 * DIMH + lane * 4];
            float4 v3 = *(const float4*)&F[s3 * DIMH + lane * 4];
            acc.x += v0.x + v1.x + v2.x + v3.x;
            acc.y += v0.y + v1.y + v2.y + v3.y;
            acc.z += v0.z + v1.z + v2.z + v3.z;
            acc.w += v0.w + v1.w + v2.w + v3.w;
        }
        for (; j < cnt; j++) {
            int s0 = __shfl_sync(0xFFFFFFFFu, idx, j);
            float4 v = *(const float4*)&F[s0 * DIMH + lane * 4];
            acc.x += v.x; acc.y += v.y; acc.z += v.z; acc.w += v.w;
        }
    }
    *(float4*)&out[warp * DIMH + lane * 4] = acc;
}

// ---------------- bf16 split tensor-core GEMM ----------------
__device__ __forceinline__ uint32_t pack_bf16(float a, float b) {
    __nv_bfloat162 p = __floats2bfloat162_rn(a, b);
    return *(uint32_t*)&p;
}
__device__ __forceinline__ void mma_bf16(float* c, const uint32_t* a, const uint32_t* b) {
    asm volatile(
        "mma.sync.aligned.m16n8k16.row.col.f32.bf16.bf16.f32 "
        "{%0,%1,%2,%3}, {%4,%5,%6,%7}, {%8,%9}, {%0,%1,%2,%3};\n"
        : "+f"(c[0]), "+f"(c[1]), "+f"(c[2]), "+f"(c[3])
        : "r"(a[0]), "r"(a[1]), "r"(a[2]), "r"(a[3]), "r"(b[0]), "r"(b[1]));
}

// Block tile 128x128x(k-chunk 32), 8 warps (2x4), warp tile 64x32.
// Smem holds bf16x2-packed k-pairs; hi and lo planes (2-term split, 3 mma/step).
#define AST 20    // A stride in uint32 kpairs: bank(g*20+tig+c) bijective
#define BST 136   // B stride in uint32: bank(tig*8+g) bijective
__global__ __launch_bounds__(256, 2) void gemm_tc_kernel(
    const float* __restrict__ A, const float* __restrict__ W,
    const float* __restrict__ bias,
    const float* __restrict__ gamma, const float* __restrict__ beta,
    const float* __restrict__ mean, const float* __restrict__ var,
    float* __restrict__ C, int M, int Kw, int mode)
{
    __shared__ uint32_t Ah[128][AST];   // [row][kpair]
    __shared__ uint32_t Al[128][AST];
    __shared__ uint32_t Bh[16][BST];    // [kpair][n]
    __shared__ uint32_t Bl[16][BST];

    const int tid  = threadIdx.x;
    const int wid  = tid >> 5;
    const int lane = tid & 31;
    const int g    = lane >> 2;
    const int tig  = lane & 3;
    const int wm   = wid & 1;
    const int wn   = wid >> 1;
    const int row0 = blockIdx.x * 128;

    float acc[4][4][4];
    #pragma unroll
    for (int mi = 0; mi < 4; mi++)
        #pragma unroll
        for (int ni = 0; ni < 4; ni++)
            #pragma unroll
            for (int r = 0; r < 4; r++) acc[mi][ni][r] = 0.0f;

    for (int k0 = 0; k0 < 128; k0 += 32) {
        // ---- A chunk 128x32: each thread 4 float4 loads; split + pack ----
        #pragma unroll
        for (int l = 0; l < 4; l++) {
            int idx = tid + l * 256;
            int r = idx >> 3, c4 = (idx & 7) * 4;   // c4 in floats
            int gr = row0 + r;
            float4 v = make_float4(0.f, 0.f, 0.f, 0.f);
            if (gr < M) v = *(const float4*)&A[gr * DIMH + k0 + c4];
            float hx = __bfloat162float(__float2bfloat16_rn(v.x));
            float hy = __bfloat162float(__float2bfloat16_rn(v.y));
            float hz = __bfloat162float(__float2bfloat16_rn(v.z));
            float hw = __bfloat162float(__float2bfloat16_rn(v.w));
            int c2 = c4 >> 1;
            Ah[r][c2]     = pack_bf16(hx, hy);
            Ah[r][c2 + 1] = pack_bf16(hz, hw);
            Al[r][c2]     = pack_bf16(v.x - hx, v.y - hy);
            Al[r][c2 + 1] = pack_bf16(v.z - hz, v.w - hw);
        }
        // ---- B chunk 32x128: thread loads 2 cells of (kpair x 4n) ----
        #pragma unroll
        for (int l = 0; l < 2; l++) {
            int idx = tid + l * 256;
            int kp = idx >> 5;            // 0..15
            int c4 = (idx & 31) * 4;      // n col
            int gk0 = k0 + 2 * kp, gk1 = gk0 + 1;
            float4 v0 = make_float4(0.f, 0.f, 0.f, 0.f);
            float4 v1 = make_float4(0.f, 0.f, 0.f, 0.f);
            if (gk0 < Kw) v0 = *(const float4*)&W[gk0 * DIMH + c4];
            if (gk1 < Kw) v1 = *(const float4*)&W[gk1 * DIMH + c4];
            float h0x = __bfloat162float(__float2bfloat16_rn(v0.x));
            float h0y = __bfloat162float(__float2bfloat16_rn(v0.y));
            float h0z = __bfloat162float(__float2bfloat16_rn(v0.z));
            float h0w = __bfloat162float(__float2bfloat16_rn(v0.w));
            float h1x = __bfloat162float(__float2bfloat16_rn(v1.x));
            float h1y = __bfloat162float(__float2bfloat16_rn(v1.y));
            float h1z = __bfloat162float(__float2bfloat16_rn(v1.z));
            float h1w = __bfloat162float(__float2bfloat16_rn(v1.w));
            Bh[kp][c4]     = pack_bf16(h0x, h1x);
            Bh[kp][c4 + 1] = pack_bf16(h0y, h1y);
            Bh[kp][c4 + 2] = pack_bf16(h0z, h1z);
            Bh[kp][c4 + 3] = pack_bf16(h0w, h1w);
            Bl[kp][c4]     = pack_bf16(v0.x - h0x, v1.x - h1x);
            Bl[kp][c4 + 1] = pack_bf16(v0.y - h0y, v1.y - h1y);
            Bl[kp][c4 + 2] = pack_bf16(v0.z - h0z, v1.z - h1z);
            Bl[kp][c4 + 3] = pack_bf16(v0.w - h0w, v1.w - h1w);
        }
        __syncthreads();

        #pragma unroll
        for (int ks = 0; ks < 2; ks++) {       // two k16 sub-chunks
            const int kk2 = ks * 8;            // kpair base
            uint32_t a_hi[4][4], a_lo[4][4];
            #pragma unroll
            for (int mi = 0; mi < 4; mi++) {
                int rm = wm * 64 + mi * 16;
                a_hi[mi][0] = Ah[rm + g    ][kk2 + tig    ];
                a_hi[mi][1] = Ah[rm + g + 8][kk2 + tig    ];
                a_hi[mi][2] = Ah[rm + g    ][kk2 + tig + 4];
                a_hi[mi][3] = Ah[rm + g + 8][kk2 + tig + 4];
                a_lo[mi][0] = Al[rm + g    ][kk2 + tig    ];
                a_lo[mi][1] = Al[rm + g + 8][kk2 + tig    ];
                a_lo[mi][2] = Al[rm + g    ][kk2 + tig + 4];
                a_lo[mi][3] = Al[rm + g + 8][kk2 + tig + 4];
            }
            #pragma unroll
            for (int ni = 0; ni < 4; ni++) {
                int cn = wn * 32 + ni * 8;
                uint32_t bh[2], bl[2];
                bh[0] = Bh[kk2 + tig    ][cn + g];
                bh[1] = Bh[kk2 + tig + 4][cn + g];
                bl[0] = Bl[kk2 + tig    ][cn + g];
                bl[1] = Bl[kk2 + tig + 4][cn + g];
                #pragma unroll
                for (int mi = 0; mi < 4; mi++) {
                    mma_bf16(acc[mi][ni], a_hi[mi], bh);
                    mma_bf16(acc[mi][ni], a_hi[mi], bl);
                    mma_bf16(acc[mi][ni], a_lo[mi], bh);
                }
            }
        }
        __syncthreads();
    }

    // ---- epilogue ----
    float sc[4][2], sh[4][2];
    #pragma unroll
    for (int ni = 0; ni < 4; ni++) {
        #pragma unroll
        for (int j = 0; j < 2; j++) {
            int c = wn * 32 + ni * 8 + 2 * tig + j;
            float b = bias[c];
            if (mode == 0) {
                float s = gamma[c] * rsqrtf(var[c] + BN_EPS);
                sc[ni][j] = s;
                sh[ni][j] = beta[c] - mean[c] * s + b * s;
            } else {
                sc[ni][j] = 1.0f;
                sh[ni][j] = b;
            }
        }
    }
    #pragma unroll
    for (int mi = 0; mi < 4; mi++) {
        int r0 = row0 + wm * 64 + mi * 16 + g;
        int r1 = r0 + 8;
        #pragma unroll
        for (int ni = 0; ni < 4; ni++) {
            int c0 = wn * 32 + ni * 8 + 2 * tig;
            if (r0 < M) {
                float2 o;
                o.x = fmaxf(acc[mi][ni][0] * sc[ni][0] + sh[ni][0], 0.0f);
                o.y = fmaxf(acc[mi][ni][1] * sc[ni][1] + sh[ni][1], 0.0f);
                *(float2*)&C[r0 * DIMH + c0] = o;
            }
            if (r1 < M) {
                float2 o;
                o.x = fmaxf(acc[mi][ni][2] * sc[ni][0] + sh[ni][0], 0.0f);
                o.y = fmaxf(acc[mi][ni][3] * sc[ni][1] + sh[ni][1], 0.0f);
                *(float2*)&C[r1 * DIMH + c0] = o;
            }
        }
    }
}

// ---------------- pooling ----------------
__global__ void pool_kernel(const int* __restrict__ batch, const float* __restrict__ h,
                            float* __restrict__ pool) {
    int i = blockIdx.x * blockDim.x + threadIdx.x;
    if (i < N_NODES * DIMH) {
        int n = i >> 7, d = i & 127;
        atomicAdd(&pool[batch[n] * DIMH + d], h[i]);
    }
}

// ---------------- head ----------------
__global__ void head_kernel(const float* __restrict__ pool,
                            const float* __restrict__ l1w, const float* __restrict__ l1b,
                            const float* __restrict__ l2w, const float* __restrict__ l2b,
                            float* __restrict__ out) {
    __shared__ float hg[DIMH];
    __shared__ float o1[LIN1_DIM];
    int gph = blockIdx.x;
    int t = threadIdx.x;  // 128
    hg[t] = pool[gph * DIMH + t];
    __syncthreads();
    if (t < LIN1_DIM) {
        float s = l1b[t];
        #pragma unroll 8
        for (int k = 0; k < DIMH; k++) s += hg[k] * l1w[k * LIN1_DIM + t];
        o1[t] = fmaxf(s, 0.0f);
    }
    __syncthreads();
    if (t == 0) {
        float s = l2b[0];
        #pragma unroll 8
        for (int j = 0; j < LIN1_DIM; j++) s += o1[j] * l2w[j];
        out[gph] = 1.0f / (1.0f + expf(-s));
    }
}

// ---------------- launch ----------------
extern "C" void kernel_launch(void* const* d_in, const int* in_sizes, int n_in,
                              void* d_out, int out_size) {
    const float* x          = (const float*)d_in[0];
    const int*   edge_index = (const int*)d_in[1];
    const int*   batch      = (const int*)d_in[2];
    const float* w[3][7];
    const float* b2[3];
    for (int l = 0; l < 3; l++) {
        int base = 3 + l * 8;
        w[l][0] = (const float*)d_in[base + 0];
        w[l][1] = (const float*)d_in[base + 1];
        w[l][2] = (const float*)d_in[base + 2];
        w[l][3] = (const float*)d_in[base + 3];
        w[l][4] = (const float*)d_in[base + 4];
        w[l][5] = (const float*)d_in[base + 5];
        w[l][6] = (const float*)d_in[base + 6];
        b2[l]   = (const float*)d_in[base + 7];
    }
    const float* l1w = (const float*)d_in[27];
    const float* l1b = (const float*)d_in[28];
    const float* l2w = (const float*)d_in[29];
    const float* l2b = (const float*)d_in[30];
    float* out = (float*)d_out;

    const int* e_src = edge_index;
    const int* e_dst = edge_index + N_EDGES;

    static float* p_feat = nullptr;
    static float* p_a    = nullptr;
    static float* p_h    = nullptr;
    static int*   p_cnt  = nullptr;
    static float* p_pool = nullptr;
    if (!p_feat) {
        cudaGetSymbolAddress((void**)&p_feat, g_feat);
        cudaGetSymbolAddress((void**)&p_a,    g_a);
        cudaGetSymbolAddress((void**)&p_h,    g_h);
        cudaGetSymbolAddress((void**)&p_cnt,  g_cnt);
        cudaGetSymbolAddress((void**)&p_pool, g_pool);
    }

    // ---- CSR build ----
    zero_int_kernel<<<(N_NODES + 255) / 256, 256>>>(p_cnt, N_NODES);
    count_kernel<<<(N_EDGES + 255) / 256, 256>>>(e_dst);
    scan_kernel<<<1, 1024>>>(N_NODES);
    scatter_kernel<<<(N_EDGES + 255) / 256, 256>>>(e_src, e_dst);

    // ---- pad x ----
    pad_x_kernel<<<(N_NODES * DIMH + 255) / 256, 256>>>(x);

    const int GEMM_GRID = (N_NODES + 127) / 128;
    const int AGG_GRID  = (N_NODES * 32 + 255) / 256;

    // ---- 3 GIN layers ----
    for (int l = 0; l < 3; l++) {
        int Kw = (l == 0) ? IN_DIM : DIMH;
        agg_kernel<<<AGG_GRID, 256>>>(p_feat, p_a);
        gemm_tc_kernel<<<GEMM_GRID, 256>>>(p_a, w[l][0], w[l][1],
                                           w[l][2], w[l][3], w[l][4], w[l][5],
                                           p_h, N_NODES, Kw, /*mode=*/0);
        gemm_tc_kernel<<<GEMM_GRID, 256>>>(p_h, w[l][6], b2[l],
                                           nullptr, nullptr, nullptr, nullptr,
                                           p_feat, N_NODES, DIMH, /*mode=*/1);
    }

    // ---- pool + head ----
    zero_float_kernel<<<(N_GRAPHS * DIMH + 255) / 256, 256>>>(p_pool, N_GRAPHS * DIMH);
    pool_kernel<<<(N_NODES * DIMH + 255) / 256, 256>>>(batch, p_feat, p_pool);
    head_kernel<<<N_GRAPHS, 128>>>(p_pool, l1w, l1b, l2w, l2b, out);
}